// round 5
// baseline (speedup 1.0000x reference)
#include <cuda_runtime.h>
#include <cstdint>
#include <cfloat>

#define Bx 8
#define Nn 1024
#define Fdim 256
#define OUTd 256
#define RELd 16
#define Rr 7

#define KC 32
#define SA_STR 36     // sA[n][k]  (row-major A), pad 4
#define ST_STR 136    // sAT[k][n] / sB[k][o], pad 8

#define ABUF 4608
#define BBUF 4352
#define HW_SMEM_FLOATS (2 * (ABUF + BBUF))   // 17920 floats = 71680 B
#define AG_STG 3
#define AG_SMEM_FLOATS (AG_STG * (ABUF + BBUF))  // 26880 floats = 107520 B

#define PSTR (Bx * Nn * OUTd)               // 2,097,152

__device__ float g_H[Rr * Bx * Nn * OUTd];  // 56 MB (tf32-rounded at store)
__device__ float g_P[4 * PSTR];             // 32 MB partials

__device__ __forceinline__ float to_tf32(float x) {
    float y; asm("cvt.rna.tf32.f32 %0, %1;" : "=f"(y) : "f"(x)); return y;
}
__device__ __forceinline__ float4 round4(float4 v) {
    v.x = to_tf32(v.x); v.y = to_tf32(v.y); v.z = to_tf32(v.z); v.w = to_tf32(v.w);
    return v;
}
__device__ __forceinline__ void mma8(float* c, const uint32_t* a, uint32_t b0, uint32_t b1) {
    asm volatile(
        "mma.sync.aligned.m16n8k8.row.col.f32.tf32.tf32.f32 "
        "{%0,%1,%2,%3}, {%4,%5,%6,%7}, {%8,%9}, {%0,%1,%2,%3};"
        : "+f"(c[0]), "+f"(c[1]), "+f"(c[2]), "+f"(c[3])
        : "r"(a[0]), "r"(a[1]), "r"(a[2]), "r"(a[3]), "r"(b0), "r"(b1));
}
__device__ __forceinline__ uint32_t fbits(const float* p) { return *(const uint32_t*)p; }
__device__ __forceinline__ uint32_t smem_u32(const void* p) {
    uint32_t a;
    asm("{ .reg .u64 t; cvta.to.shared.u64 t, %1; cvt.u32.u64 %0, t; }" : "=r"(a) : "l"(p));
    return a;
}
#define CPA16(dst, src) \
    asm volatile("cp.async.cg.shared.global [%0], [%1], 16;" :: "r"(dst), "l"(src))
#define CPA_COMMIT() asm volatile("cp.async.commit_group;" ::: "memory")
#define CPA_WAIT2()  asm volatile("cp.async.wait_group 2;" ::: "memory")
#define CPA_WAIT1()  asm volatile("cp.async.wait_group 1;" ::: "memory")
#define CPA_WAIT0()  asm volatile("cp.async.wait_group 0;" ::: "memory")

// ---------------------------------------------------------------------------
// HW GEMM: g_H[r][b][n][o] = tf32( X[b,n,:]@W[r][:F] + c[r] ).  Tile 128x128.
__global__ __launch_bounds__(256) void hw_mma(const float* __restrict__ X,
                                              const float* __restrict__ W,
                                              const float* __restrict__ We) {
    extern __shared__ float sm[];
    __shared__ float sCv[128];
    float* sA[2] = { sm, sm + ABUF };
    float* sB[2] = { sm + 2 * ABUF, sm + 2 * ABUF + BBUF };

    const int tid = threadIdx.x, lane = tid & 31, wid = tid >> 5;
    const int warp_m = (wid & 3) * 32, warp_n = (wid >> 2) * 64;
    const int grp = lane >> 2, tg = lane & 3;

    const int col0 = blockIdx.x * 128;
    const int m0   = blockIdx.y * 128;
    const int r    = col0 >> 8;
    const int o0   = col0 & 255;
    const float* Wr = W + (size_t)r * (Fdim + RELd) * OUTd;

    if (tid < 128) {
        float s = 0.f;
#pragma unroll
        for (int d = 0; d < RELd; d++)
            s += We[r * RELd + d] * Wr[(size_t)(Fdim + d) * OUTd + o0 + tid];
        sCv[tid] = s;
    }

    float acc[2][8][4];
#pragma unroll
    for (int mt = 0; mt < 2; mt++)
#pragma unroll
        for (int nt = 0; nt < 8; nt++)
#pragma unroll
            for (int j = 0; j < 4; j++) acc[mt][nt][j] = 0.f;

#pragma unroll
    for (int i = 0; i < 4; i++) {
        int f = tid + i * 256, m = f >> 3, k4 = (f & 7) << 2;
        float4 v = round4(*(const float4*)(X + (size_t)(m0 + m) * Fdim + k4));
        *(float4*)(sA[0] + m * SA_STR + k4) = v;
        int kb = f >> 5, ob4 = (f & 31) << 2;
        float4 w = round4(*(const float4*)(Wr + (size_t)kb * OUTd + o0 + ob4));
        *(float4*)(sB[0] + kb * ST_STR + ob4) = w;
    }
    __syncthreads();

    const int NC = Fdim / KC;  // 8
    for (int c = 0; c < NC; c++) {
        const int buf = c & 1;
        float4 ra[4], rb[4];
        const bool pre = (c + 1 < NC);
        if (pre) {
            const int k0 = (c + 1) * KC;
#pragma unroll
            for (int i = 0; i < 4; i++) {
                int f = tid + i * 256, m = f >> 3, k4 = (f & 7) << 2;
                ra[i] = *(const float4*)(X + (size_t)(m0 + m) * Fdim + k0 + k4);
                int kb = f >> 5, ob4 = (f & 31) << 2;
                rb[i] = *(const float4*)(Wr + (size_t)(k0 + kb) * OUTd + o0 + ob4);
            }
        }
        const float* cA = sA[buf];
        const float* cB = sB[buf];
#pragma unroll
        for (int ks = 0; ks < 4; ks++) {
            const int k = ks * 8;
            uint32_t afr[2][4];
#pragma unroll
            for (int mt = 0; mt < 2; mt++) {
                int rr = warp_m + mt * 16 + grp, cc = k + tg;
                afr[mt][0] = fbits(cA + rr * SA_STR + cc);
                afr[mt][1] = fbits(cA + (rr + 8) * SA_STR + cc);
                afr[mt][2] = fbits(cA + rr * SA_STR + cc + 4);
                afr[mt][3] = fbits(cA + (rr + 8) * SA_STR + cc + 4);
            }
#pragma unroll
            for (int nt = 0; nt < 8; nt++) {
                int o = warp_n + nt * 8 + grp;
                uint32_t b0 = fbits(cB + (k + tg) * ST_STR + o);
                uint32_t b1 = fbits(cB + (k + tg + 4) * ST_STR + o);
                mma8(acc[0][nt], afr[0], b0, b1);
                mma8(acc[1][nt], afr[1], b0, b1);
            }
        }
        if (pre) {
            float* nA = sA[buf ^ 1];
            float* nB = sB[buf ^ 1];
#pragma unroll
            for (int i = 0; i < 4; i++) {
                int f = tid + i * 256, m = f >> 3, k4 = (f & 7) << 2;
                *(float4*)(nA + m * SA_STR + k4) = round4(ra[i]);
                int kb = f >> 5, ob4 = (f & 31) << 2;
                *(float4*)(nB + kb * ST_STR + ob4) = round4(rb[i]);
            }
            __syncthreads();
        }
    }

#pragma unroll
    for (int mt = 0; mt < 2; mt++) {
#pragma unroll
        for (int nt = 0; nt < 8; nt++) {
            const int ol = warp_n + nt * 8 + 2 * tg;
            const float2 cv = *(const float2*)(sCv + ol);
            const int o = o0 + ol;
            int mg = m0 + warp_m + mt * 16 + grp;
            int b = mg >> 10, n = mg & 1023;
            float* dst = g_H + (((size_t)(r * Bx + b) * Nn + n) * OUTd) + o;
            *(float2*)dst = make_float2(to_tf32(acc[mt][nt][0] + cv.x),
                                        to_tf32(acc[mt][nt][1] + cv.y));
            mg += 8; b = mg >> 10; n = mg & 1023;
            dst = g_H + (((size_t)(r * Bx + b) * Nn + n) * OUTd) + o;
            *(float2*)dst = make_float2(to_tf32(acc[mt][nt][2] + cv.x),
                                        to_tf32(acc[mt][nt][3] + cv.y));
        }
    }
}

// ---------------------------------------------------------------------------
// One relation pass: P[p][b] = A(_or_At) @ H[hwr].  3-stage cp.async pipeline.
template <bool TR>
__device__ __forceinline__ void agg_load(uint32_t sa, uint32_t sb,
                                         const float* Ab, const float* Hb,
                                         int n0, int o0, int k0, int tid) {
#pragma unroll
    for (int i = 0; i < 4; i++) {
        int f = tid + i * 256;
        if (!TR) {
            int m = f >> 3, k4 = (f & 7) << 2;
            CPA16(sa + (m * SA_STR + k4) * 4, Ab + (size_t)(n0 + m) * Nn + k0 + k4);
        } else {
            int kk = f >> 5, n4 = (f & 31) << 2;
            CPA16(sa + (kk * ST_STR + n4) * 4, Ab + (size_t)(k0 + kk) * Nn + n0 + n4);
        }
        int kb = f >> 5, ob4 = (f & 31) << 2;
        CPA16(sb + (kb * ST_STR + ob4) * 4, Hb + (size_t)(k0 + kb) * OUTd + o0 + ob4);
    }
}

template <bool TR>
__device__ __forceinline__ void agg_ldA(uint32_t* afr, const float* cA,
                                        int warp_m, int grp, int tg, int k) {
#pragma unroll
    for (int mt = 0; mt < 2; mt++) {
        int rr = warp_m + mt * 16 + grp, cc = k + tg;
        if (!TR) {
            afr[mt * 4 + 0] = fbits(cA + rr * SA_STR + cc);
            afr[mt * 4 + 1] = fbits(cA + (rr + 8) * SA_STR + cc);
            afr[mt * 4 + 2] = fbits(cA + rr * SA_STR + cc + 4);
            afr[mt * 4 + 3] = fbits(cA + (rr + 8) * SA_STR + cc + 4);
        } else {
            afr[mt * 4 + 0] = fbits(cA + cc * ST_STR + rr);
            afr[mt * 4 + 1] = fbits(cA + cc * ST_STR + rr + 8);
            afr[mt * 4 + 2] = fbits(cA + (cc + 4) * ST_STR + rr);
            afr[mt * 4 + 3] = fbits(cA + (cc + 4) * ST_STR + rr + 8);
        }
    }
}

template <bool TR>
__device__ __forceinline__ void agg_body(const float* Ab, const float* Hb,
                                         float* Pout, int n0, int o0) {
    extern __shared__ float sm[];
    float* sA[AG_STG]; float* sB[AG_STG];
#pragma unroll
    for (int i = 0; i < AG_STG; i++) {
        sA[i] = sm + i * ABUF;
        sB[i] = sm + AG_STG * ABUF + i * BBUF;
    }
    uint32_t saU[AG_STG], sbU[AG_STG];
#pragma unroll
    for (int i = 0; i < AG_STG; i++) { saU[i] = smem_u32(sA[i]); sbU[i] = smem_u32(sB[i]); }

    const int tid = threadIdx.x, lane = tid & 31, wid = tid >> 5;
    const int warp_m = (wid & 3) * 32, warp_n = (wid >> 2) * 64;
    const int grp = lane >> 2, tg = lane & 3;

    float acc[2][8][4];
#pragma unroll
    for (int mt = 0; mt < 2; mt++)
#pragma unroll
        for (int nt = 0; nt < 8; nt++)
#pragma unroll
            for (int j = 0; j < 4; j++) acc[mt][nt][j] = 0.f;

    const int NC = Nn / KC;  // 32
#pragma unroll
    for (int s = 0; s < AG_STG; s++) {
        agg_load<TR>(saU[s], sbU[s], Ab, Hb, n0, o0, s * KC, tid);
        CPA_COMMIT();
    }

    int buf = 0;
    for (int c = 0; c < NC; c++) {
        if (c <= NC - AG_STG) CPA_WAIT2();
        else if (c == NC - 2)  CPA_WAIT1();
        else                   CPA_WAIT0();
        __syncthreads();

        const float* cA = sA[buf];
        const float* cB = sB[buf];

        uint32_t afr[2][8];
        agg_ldA<TR>(afr[0], cA, warp_m, grp, tg, 0);
#pragma unroll
        for (int ks = 0; ks < 4; ks++) {
            if (ks < 3) agg_ldA<TR>(afr[(ks + 1) & 1], cA, warp_m, grp, tg, (ks + 1) * 8);
            const uint32_t* af = afr[ks & 1];
            const int k = ks * 8;
#pragma unroll
            for (int nt = 0; nt < 8; nt++) {
                int o = warp_n + nt * 8 + grp;
                uint32_t b0 = fbits(cB + (k + tg) * ST_STR + o);
                uint32_t b1 = fbits(cB + (k + tg + 4) * ST_STR + o);
                mma8(acc[0][nt], af, b0, b1);
                mma8(acc[1][nt], af + 4, b0, b1);
            }
        }
        if (c + AG_STG < NC) {
            __syncthreads();
            agg_load<TR>(saU[buf], sbU[buf], Ab, Hb, n0, o0, (c + AG_STG) * KC, tid);
            CPA_COMMIT();
        }
        buf = (buf + 1 == AG_STG) ? 0 : buf + 1;
    }

#pragma unroll
    for (int mt = 0; mt < 2; mt++) {
#pragma unroll
        for (int nt = 0; nt < 8; nt++) {
            const int o = o0 + warp_n + nt * 8 + 2 * tg;
#pragma unroll
            for (int h = 0; h < 2; h++) {
                const int n = n0 + warp_m + mt * 16 + grp + h * 8;
                *(float2*)(Pout + (size_t)n * OUTd + o) =
                    make_float2(acc[mt][nt][2 * h], acc[mt][nt][2 * h + 1]);
            }
        }
    }
}

__global__ __launch_bounds__(256, 2) void agg_pass(const float* __restrict__ A1,
                                                   const float* __restrict__ A2) {
    const int o0 = blockIdx.x * 128;
    const int n0 = blockIdx.y * 128;
    const int z  = blockIdx.z;
    const int b  = z & 7;
    const int p  = z >> 3;
    const int q  = p & 1;
    const float* Ab = (q == 0 ? A1 : A2) + (size_t)b * Nn * Nn;
    const int hwr = (p >> 1) * 3 + q;        // 0,1,3,4
    const float* Hb = g_H + ((size_t)(hwr * Bx + b) * Nn) * OUTd;
    float* Pout = g_P + (size_t)p * PSTR + ((size_t)b * Nn) * OUTd;

    if (p < 2) agg_body<false>(Ab, Hb, Pout, n0, o0);
    else       agg_body<true >(Ab, Hb, Pout, n0, o0);
}

// ---------------------------------------------------------------------------
__global__ __launch_bounds__(256) void fold_kernel(const float* __restrict__ bias,
                                                   float* __restrict__ out) {
    const int idx = (blockIdx.x * 256 + threadIdx.x) * 4;
    float4 v = *(const float4*)(g_P + idx);
    float4 t;
#pragma unroll
    for (int p = 1; p < 4; p++) {
        t = *(const float4*)(g_P + (size_t)p * PSTR + idx);
        v.x = fmaxf(v.x, t.x); v.y = fmaxf(v.y, t.y);
        v.z = fmaxf(v.z, t.z); v.w = fmaxf(v.w, t.w);
    }
#pragma unroll
    for (int rr = 0; rr < 3; rr++) {
        const int r = (rr == 0) ? 2 : (rr == 1) ? 5 : 6;
        t = *(const float4*)(g_H + (size_t)r * PSTR + idx);
        v.x = fmaxf(v.x, t.x); v.y = fmaxf(v.y, t.y);
        v.z = fmaxf(v.z, t.z); v.w = fmaxf(v.w, t.w);
    }
    const int bi = idx & (Nn * OUTd - 1);
    t = *(const float4*)(bias + bi);
    v.x += t.x; v.y += t.y; v.z += t.z; v.w += t.w;
    *(float4*)(out + idx) = v;
}

// ---------------------------------------------------------------------------
extern "C" void kernel_launch(void* const* d_in, const int* in_sizes, int n_in,
                              void* d_out, int out_size) {
    const float* X    = (const float*)d_in[0];
    const float* A1   = (const float*)d_in[1];
    const float* A2   = (const float*)d_in[2];
    const float* W    = (const float*)d_in[3];
    const float* We   = (const float*)d_in[4];
    const float* bias = (const float*)d_in[5];
    float* out = (float*)d_out;

    const int hw_smem = HW_SMEM_FLOATS * sizeof(float);
    const int ag_smem = AG_SMEM_FLOATS * sizeof(float);
    cudaFuncSetAttribute(hw_mma,   cudaFuncAttributeMaxDynamicSharedMemorySize, hw_smem);
    cudaFuncSetAttribute(agg_pass, cudaFuncAttributeMaxDynamicSharedMemorySize, ag_smem);

    dim3 gHW(14, 64);
    hw_mma<<<gHW, 256, hw_smem>>>(X, W, We);

    dim3 gAgg(2, 8, 32);
    agg_pass<<<gAgg, 256, ag_smem>>>(A1, A2);

    fold_kernel<<<(Bx * Nn * OUTd) / 1024, 256>>>(bias, out);
}

// round 6
// speedup vs baseline: 1.1324x; 1.1324x over previous
#include <cuda_runtime.h>
#include <cstdint>
#include <cfloat>

#define Bx 8
#define Nn 1024
#define Fdim 256
#define OUTd 256
#define RELd 16
#define Rr 7

#define KC 32
#define SA_STR 36     // sA[n][k] (row-major A) / sAT[k][n] uses ST_STR
#define ST_STR 136    // sAT[k][n] and hw's sB[k][o], pad 8
#define SB_STR 40     // agg's sB[o][k'] rows: 32 data + 8 pad (conflict-free LDS.64)

#define ABUF 4608                           // max(128*36, 32*136)
#define BBUF_HW 4352                        // 32*136
#define BBUF_AG 5120                        // 128*40
#define HW_SMEM_FLOATS (2 * (ABUF + BBUF_HW))   // 17920 floats
#define AG_SMEM_FLOATS (2 * (ABUF + BBUF_AG))   // 19456 floats = 77824 B

#define PSTR (Bx * Nn * OUTd)               // 2,097,152

__device__ float g_Ht[4 * PSTR];            // 32 MB: relations 0,1,3,4 as [o][m'] (tf32)
__device__ float g_H3[3 * PSTR];            // 24 MB: identities 2,5,6 as [n][o] (tf32)
__device__ float g_P[4 * PSTR];             // 32 MB partials

__device__ __forceinline__ float to_tf32(float x) {
    float y; asm("cvt.rna.tf32.f32 %0, %1;" : "=f"(y) : "f"(x)); return y;
}
__device__ __forceinline__ float4 round4(float4 v) {
    v.x = to_tf32(v.x); v.y = to_tf32(v.y); v.z = to_tf32(v.z); v.w = to_tf32(v.w);
    return v;
}
__device__ __forceinline__ void mma8(float* c, const uint32_t* a, uint32_t b0, uint32_t b1) {
    asm volatile(
        "mma.sync.aligned.m16n8k8.row.col.f32.tf32.tf32.f32 "
        "{%0,%1,%2,%3}, {%4,%5,%6,%7}, {%8,%9}, {%0,%1,%2,%3};"
        : "+f"(c[0]), "+f"(c[1]), "+f"(c[2]), "+f"(c[3])
        : "r"(a[0]), "r"(a[1]), "r"(a[2]), "r"(a[3]), "r"(b0), "r"(b1));
}
__device__ __forceinline__ uint32_t fbits(const float* p) { return *(const uint32_t*)p; }
__device__ __forceinline__ uint32_t smem_u32(const void* p) {
    uint32_t a;
    asm("{ .reg .u64 t; cvta.to.shared.u64 t, %1; cvt.u32.u64 %0, t; }" : "=r"(a) : "l"(p));
    return a;
}
// octet permutation: position for original in-octet index j
__device__ __forceinline__ int operm(int n) {
    return (n & ~7) | (((n & 3) << 1) | ((n >> 2) & 1));
}
#define CPA16(dst, src) \
    asm volatile("cp.async.cg.shared.global [%0], [%1], 16;" :: "r"(dst), "l"(src))
#define CPA_COMMIT() asm volatile("cp.async.commit_group;" ::: "memory")
#define CPA_WAIT1()  asm volatile("cp.async.wait_group 1;" ::: "memory")
#define CPA_WAIT0()  asm volatile("cp.async.wait_group 0;" ::: "memory")

// ---------------------------------------------------------------------------
// HW GEMM: tf32( X[b,n,:]@W[r][:F] + c[r] ) -> g_Ht (r=0,1,3,4) or g_H3 (r=2,5,6)
__global__ __launch_bounds__(256) void hw_mma(const float* __restrict__ X,
                                              const float* __restrict__ W,
                                              const float* __restrict__ We) {
    extern __shared__ float sm[];
    __shared__ float sCv[128];
    float* sA[2] = { sm, sm + ABUF };
    float* sB[2] = { sm + 2 * ABUF, sm + 2 * ABUF + BBUF_HW };

    const int tid = threadIdx.x, lane = tid & 31, wid = tid >> 5;
    const int warp_m = (wid & 3) * 32, warp_n = (wid >> 2) * 64;
    const int grp = lane >> 2, tg = lane & 3;

    const int col0 = blockIdx.x * 128;
    const int m0   = blockIdx.y * 128;
    const int r    = col0 >> 8;
    const int o0   = col0 & 255;
    const float* Wr = W + (size_t)r * (Fdim + RELd) * OUTd;

    if (tid < 128) {
        float s = 0.f;
#pragma unroll
        for (int d = 0; d < RELd; d++)
            s += We[r * RELd + d] * Wr[(size_t)(Fdim + d) * OUTd + o0 + tid];
        sCv[tid] = s;
    }

    float acc[2][8][4];
#pragma unroll
    for (int mt = 0; mt < 2; mt++)
#pragma unroll
        for (int nt = 0; nt < 8; nt++)
#pragma unroll
            for (int j = 0; j < 4; j++) acc[mt][nt][j] = 0.f;

#pragma unroll
    for (int i = 0; i < 4; i++) {
        int f = tid + i * 256, m = f >> 3, k4 = (f & 7) << 2;
        float4 v = round4(*(const float4*)(X + (size_t)(m0 + m) * Fdim + k4));
        *(float4*)(sA[0] + m * SA_STR + k4) = v;
        int kb = f >> 5, ob4 = (f & 31) << 2;
        float4 w = round4(*(const float4*)(Wr + (size_t)kb * OUTd + o0 + ob4));
        *(float4*)(sB[0] + kb * ST_STR + ob4) = w;
    }
    __syncthreads();

    const int NC = Fdim / KC;  // 8
    for (int c = 0; c < NC; c++) {
        const int buf = c & 1;
        float4 ra[4], rb[4];
        const bool pre = (c + 1 < NC);
        if (pre) {
            const int k0 = (c + 1) * KC;
#pragma unroll
            for (int i = 0; i < 4; i++) {
                int f = tid + i * 256, m = f >> 3, k4 = (f & 7) << 2;
                ra[i] = *(const float4*)(X + (size_t)(m0 + m) * Fdim + k0 + k4);
                int kb = f >> 5, ob4 = (f & 31) << 2;
                rb[i] = *(const float4*)(Wr + (size_t)(k0 + kb) * OUTd + o0 + ob4);
            }
        }
        const float* cA = sA[buf];
        const float* cB = sB[buf];
#pragma unroll
        for (int ks = 0; ks < 4; ks++) {
            const int k = ks * 8;
            uint32_t afr[2][4];
#pragma unroll
            for (int mt = 0; mt < 2; mt++) {
                int rr = warp_m + mt * 16 + grp, cc = k + tg;
                afr[mt][0] = fbits(cA + rr * SA_STR + cc);
                afr[mt][1] = fbits(cA + (rr + 8) * SA_STR + cc);
                afr[mt][2] = fbits(cA + rr * SA_STR + cc + 4);
                afr[mt][3] = fbits(cA + (rr + 8) * SA_STR + cc + 4);
            }
#pragma unroll
            for (int nt = 0; nt < 8; nt++) {
                int o = warp_n + nt * 8 + grp;
                uint32_t b0 = fbits(cB + (k + tg) * ST_STR + o);
                uint32_t b1 = fbits(cB + (k + tg + 4) * ST_STR + o);
                mma8(acc[0][nt], afr[0], b0, b1);
                mma8(acc[1][nt], afr[1], b0, b1);
            }
        }
        if (pre) {
            float* nA = sA[buf ^ 1];
            float* nB = sB[buf ^ 1];
#pragma unroll
            for (int i = 0; i < 4; i++) {
                int f = tid + i * 256, m = f >> 3, k4 = (f & 7) << 2;
                *(float4*)(nA + m * SA_STR + k4) = round4(ra[i]);
                int kb = f >> 5, ob4 = (f & 31) << 2;
                *(float4*)(nB + kb * ST_STR + ob4) = round4(rb[i]);
            }
            __syncthreads();
        }
    }

    const bool isId = (r == 2 || r == 5 || r == 6);
    if (isId) {
        const int zi = (r == 2) ? 0 : (r == 5) ? 1 : 2;
#pragma unroll
        for (int mt = 0; mt < 2; mt++) {
#pragma unroll
            for (int nt = 0; nt < 8; nt++) {
                const int ol = warp_n + nt * 8 + 2 * tg;
                const float2 cv = *(const float2*)(sCv + ol);
                const int o = o0 + ol;
                int mg = m0 + warp_m + mt * 16 + grp;
                int b = mg >> 10, n = mg & 1023;
                float* dst = g_H3 + (((size_t)(zi * Bx + b) * Nn + n) * OUTd) + o;
                *(float2*)dst = make_float2(to_tf32(acc[mt][nt][0] + cv.x),
                                            to_tf32(acc[mt][nt][1] + cv.y));
                mg += 8; b = mg >> 10; n = mg & 1023;
                dst = g_H3 + (((size_t)(zi * Bx + b) * Nn + n) * OUTd) + o;
                *(float2*)dst = make_float2(to_tf32(acc[mt][nt][2] + cv.x),
                                            to_tf32(acc[mt][nt][3] + cv.y));
            }
        }
    } else {
        const int ti = (r < 2) ? r : r - 1;   // 0,1,3,4 -> 0,1,2,3
#pragma unroll
        for (int mt = 0; mt < 2; mt++) {
#pragma unroll
            for (int nt = 0; nt < 8; nt++) {
                const int ol = warp_n + nt * 8 + 2 * tg;
                const float2 cv = *(const float2*)(sCv + ol);
                const int o = o0 + ol;
                int mg = m0 + warp_m + mt * 16 + grp;
                {
                    int b = mg >> 10, n = mg & 1023, np = operm(n);
                    float* base = g_Ht + ((size_t)(ti * Bx + b) * OUTd + o) * Nn;
                    base[np]      = to_tf32(acc[mt][nt][0] + cv.x);
                    base[Nn + np] = to_tf32(acc[mt][nt][1] + cv.y);
                }
                mg += 8;
                {
                    int b = mg >> 10, n = mg & 1023, np = operm(n);
                    float* base = g_Ht + ((size_t)(ti * Bx + b) * OUTd + o) * Nn;
                    base[np]      = to_tf32(acc[mt][nt][2] + cv.x);
                    base[Nn + np] = to_tf32(acc[mt][nt][3] + cv.y);
                }
            }
        }
    }
}

// ---------------------------------------------------------------------------
// One relation pass: P[p][b] = A(_or_At) @ H.  2-stage cp.async, float2 B frags.
template <bool TR>
__device__ __forceinline__ void agg_load(uint32_t sa, uint32_t sb,
                                         const float* Ab, const float* Hb,
                                         int n0, int k0, int tid) {
#pragma unroll
    for (int i = 0; i < 4; i++) {
        int f = tid + i * 256;
        if (!TR) {
            int m = f >> 3, k4 = (f & 7) << 2;
            CPA16(sa + (m * SA_STR + k4) * 4, Ab + (size_t)(n0 + m) * Nn + k0 + k4);
        } else {
            int kk = f >> 5, n4 = (f & 31) << 2;
            CPA16(sa + (kk * ST_STR + n4) * 4, Ab + (size_t)(k0 + kk) * Nn + n0 + n4);
        }
        // B: sB[o][k'] rows of 32 floats from g_Ht (already transposed+permuted)
        int o = f >> 3, s4 = (f & 7) << 2;
        CPA16(sb + (o * SB_STR + s4) * 4, Hb + (size_t)o * Nn + k0 + s4);
    }
}

template <bool TR>
__device__ __forceinline__ void agg_body(const float* Ab, const float* Hb,
                                         float* Pout, int n0, int o0) {
    extern __shared__ float sm[];
    float* sA[2] = { sm, sm + ABUF };
    float* sB[2] = { sm + 2 * ABUF, sm + 2 * ABUF + BBUF_AG };
    const uint32_t saU[2] = { smem_u32(sA[0]), smem_u32(sA[1]) };
    const uint32_t sbU[2] = { smem_u32(sB[0]), smem_u32(sB[1]) };

    const int tid = threadIdx.x, lane = tid & 31, wid = tid >> 5;
    const int warp_m = (wid & 3) * 32, warp_n = (wid >> 2) * 64;
    const int grp = lane >> 2, tg = lane & 3;

    float acc[2][8][4];
#pragma unroll
    for (int mt = 0; mt < 2; mt++)
#pragma unroll
        for (int nt = 0; nt < 8; nt++)
#pragma unroll
            for (int j = 0; j < 4; j++) acc[mt][nt][j] = 0.f;

    const int NC = Nn / KC;  // 32
    agg_load<TR>(saU[0], sbU[0], Ab, Hb, n0, 0, tid);
    CPA_COMMIT();
    agg_load<TR>(saU[1], sbU[1], Ab, Hb, n0, KC, tid);
    CPA_COMMIT();

    for (int c = 0; c < NC; c++) {
        const int buf = c & 1;
        if (c + 1 < NC) CPA_WAIT1(); else CPA_WAIT0();
        __syncthreads();

        const float* cA = sA[buf];
        const float* cB = sB[buf] + (warp_n + grp) * SB_STR + 2 * tg;
#pragma unroll
        for (int ks = 0; ks < 4; ks++) {
            const int k = ks * 8;
            uint32_t afr[2][4];
#pragma unroll
            for (int mt = 0; mt < 2; mt++) {
                int rr = warp_m + mt * 16 + grp, cc = k + tg;
                if (!TR) {
                    afr[mt][0] = fbits(cA + rr * SA_STR + cc);
                    afr[mt][1] = fbits(cA + (rr + 8) * SA_STR + cc);
                    afr[mt][2] = fbits(cA + rr * SA_STR + cc + 4);
                    afr[mt][3] = fbits(cA + (rr + 8) * SA_STR + cc + 4);
                } else {
                    afr[mt][0] = fbits(cA + cc * ST_STR + rr);
                    afr[mt][1] = fbits(cA + cc * ST_STR + rr + 8);
                    afr[mt][2] = fbits(cA + (cc + 4) * ST_STR + rr);
                    afr[mt][3] = fbits(cA + (cc + 4) * ST_STR + rr + 8);
                }
            }
#pragma unroll
            for (int nt = 0; nt < 8; nt++) {
                const float2 bv = *(const float2*)(cB + nt * 8 * SB_STR + k);
                uint32_t b0 = fbits(&bv.x), b1 = fbits(&bv.y);
                mma8(acc[0][nt], afr[0], b0, b1);
                mma8(acc[1][nt], afr[1], b0, b1);
            }
        }
        if (c + 2 < NC) {
            __syncthreads();
            agg_load<TR>(saU[buf], sbU[buf], Ab, Hb, n0, (c + 2) * KC, tid);
            CPA_COMMIT();
        }
    }

#pragma unroll
    for (int mt = 0; mt < 2; mt++) {
#pragma unroll
        for (int nt = 0; nt < 8; nt++) {
            const int o = o0 + warp_n + nt * 8 + 2 * tg;
#pragma unroll
            for (int h = 0; h < 2; h++) {
                const int n = n0 + warp_m + mt * 16 + grp + h * 8;
                *(float2*)(Pout + (size_t)n * OUTd + o) =
                    make_float2(acc[mt][nt][2 * h], acc[mt][nt][2 * h + 1]);
            }
        }
    }
}

__global__ __launch_bounds__(256, 2) void agg_pass(const float* __restrict__ A1,
                                                   const float* __restrict__ A2) {
    const int o0 = blockIdx.x * 128;
    const int n0 = blockIdx.y * 128;
    const int z  = blockIdx.z;
    const int b  = z & 7;
    const int p  = z >> 3;                   // 0:A1@H0 1:A2@H1 2:A1t@H3 3:A2t@H4
    const int q  = p & 1;
    const float* Ab = (q == 0 ? A1 : A2) + (size_t)b * Nn * Nn;
    const float* Hb = g_Ht + ((size_t)(p * Bx + b) * OUTd + o0) * Nn;
    float* Pout = g_P + (size_t)p * PSTR + ((size_t)b * Nn) * OUTd;

    if (p < 2) agg_body<false>(Ab, Hb, Pout, n0, o0);
    else       agg_body<true >(Ab, Hb, Pout, n0, o0);
}

// ---------------------------------------------------------------------------
__global__ __launch_bounds__(256) void fold_kernel(const float* __restrict__ bias,
                                                   float* __restrict__ out) {
    const int idx = (blockIdx.x * 256 + threadIdx.x) * 4;
    float4 v = *(const float4*)(g_P + idx);
    float4 t;
#pragma unroll
    for (int p = 1; p < 4; p++) {
        t = *(const float4*)(g_P + (size_t)p * PSTR + idx);
        v.x = fmaxf(v.x, t.x); v.y = fmaxf(v.y, t.y);
        v.z = fmaxf(v.z, t.z); v.w = fmaxf(v.w, t.w);
    }
#pragma unroll
    for (int zi = 0; zi < 3; zi++) {
        t = *(const float4*)(g_H3 + (size_t)zi * PSTR + idx);
        v.x = fmaxf(v.x, t.x); v.y = fmaxf(v.y, t.y);
        v.z = fmaxf(v.z, t.z); v.w = fmaxf(v.w, t.w);
    }
    const int bi = idx & (Nn * OUTd - 1);
    t = *(const float4*)(bias + bi);
    v.x += t.x; v.y += t.y; v.z += t.z; v.w += t.w;
    *(float4*)(out + idx) = v;
}

// ---------------------------------------------------------------------------
extern "C" void kernel_launch(void* const* d_in, const int* in_sizes, int n_in,
                              void* d_out, int out_size) {
    const float* X    = (const float*)d_in[0];
    const float* A1   = (const float*)d_in[1];
    const float* A2   = (const float*)d_in[2];
    const float* W    = (const float*)d_in[3];
    const float* We   = (const float*)d_in[4];
    const float* bias = (const float*)d_in[5];
    float* out = (float*)d_out;

    const int hw_smem = HW_SMEM_FLOATS * sizeof(float);
    const int ag_smem = AG_SMEM_FLOATS * sizeof(float);
    cudaFuncSetAttribute(hw_mma,   cudaFuncAttributeMaxDynamicSharedMemorySize, hw_smem);
    cudaFuncSetAttribute(agg_pass, cudaFuncAttributeMaxDynamicSharedMemorySize, ag_smem);

    dim3 gHW(14, 64);
    hw_mma<<<gHW, 256, hw_smem>>>(X, W, We);

    dim3 gAgg(2, 8, 32);
    agg_pass<<<gAgg, 256, ag_smem>>>(A1, A2);

    fold_kernel<<<(Bx * Nn * OUTd) / 1024, 256>>>(bias, out);
}

// round 7
// speedup vs baseline: 1.1326x; 1.0002x over previous
#include <cuda_runtime.h>
#include <cstdint>
#include <cfloat>

#define Bx 8
#define Nn 1024
#define Fdim 256
#define OUTd 256
#define RELd 16
#define Rr 7

#define KC 32
#define SA_STR 36     // agg: sA[n][k] (row-major A)
#define ST_STR 136    // agg: sAT[k][n]
#define SB_STR 40     // k'-permuted rows: 32 data + 8 pad (conflict-free LDS.64)

#define ABUF 4608                            // max(128*36, 32*136)
#define BBUF_AG 5120                         // 128*40
#define AG_SMEM_FLOATS (2 * (ABUF + BBUF_AG))    // 19456 floats = 77824 B
#define XWBUF 5120                           // 128*40
#define HW_SMEM_FLOATS (4 * XWBUF)               // 20480 floats = 81920 B

#define PSTR (Bx * Nn * OUTd)                // 2,097,152

__device__ float g_Ht[4 * PSTR];             // relations 0,1,3,4 as [o][m'] (tf32)
__device__ float g_H3[3 * PSTR];             // identities 2,5,6 as [n][o] (tf32)
__device__ float g_P[4 * PSTR];              // partials
__device__ float g_Xr[Bx * Nn * Fdim];       // X rna-rounded, k-permuted
__device__ float g_Wt[Rr * OUTd * Fdim];     // W transposed [r][o][k'], rna, k-permuted

__device__ __forceinline__ float to_tf32(float x) {
    float y; asm("cvt.rna.tf32.f32 %0, %1;" : "=f"(y) : "f"(x)); return y;
}
__device__ __forceinline__ float4 round4(float4 v) {
    v.x = to_tf32(v.x); v.y = to_tf32(v.y); v.z = to_tf32(v.z); v.w = to_tf32(v.w);
    return v;
}
__device__ __forceinline__ void mma8(float* c, const uint32_t* a, uint32_t b0, uint32_t b1) {
    asm volatile(
        "mma.sync.aligned.m16n8k8.row.col.f32.tf32.tf32.f32 "
        "{%0,%1,%2,%3}, {%4,%5,%6,%7}, {%8,%9}, {%0,%1,%2,%3};"
        : "+f"(c[0]), "+f"(c[1]), "+f"(c[2]), "+f"(c[3])
        : "r"(a[0]), "r"(a[1]), "r"(a[2]), "r"(a[3]), "r"(b0), "r"(b1));
}
__device__ __forceinline__ uint32_t fbits(const float* p) { return *(const uint32_t*)p; }
__device__ __forceinline__ uint32_t smem_u32(const void* p) {
    uint32_t a;
    asm("{ .reg .u64 t; cvta.to.shared.u64 t, %1; cvt.u32.u64 %0, t; }" : "=r"(a) : "l"(p));
    return a;
}
// octet permutation of contraction index: pairs (k, k+4) become adjacent
__device__ __forceinline__ int operm(int n) {
    return (n & ~7) | (((n & 3) << 1) | ((n >> 2) & 1));
}
#define CPA16(dst, src) \
    asm volatile("cp.async.cg.shared.global [%0], [%1], 16;" :: "r"(dst), "l"(src))
#define CPA_COMMIT() asm volatile("cp.async.commit_group;" ::: "memory")
#define CPA_WAIT1()  asm volatile("cp.async.wait_group 1;" ::: "memory")
#define CPA_WAIT0()  asm volatile("cp.async.wait_group 0;" ::: "memory")

// ---------------------------------------------------------------------------
// Prep: g_Xr[m][k'] = rna(X[m][k])
__global__ void xp_kernel(const float* __restrict__ X) {
    int f = blockIdx.x * 256 + threadIdx.x;       // 524288 threads
    int m = f >> 6, k4 = (f & 63) << 2;
    float4 v = round4(*(const float4*)(X + (size_t)m * Fdim + k4));
    float* dst = g_Xr + (size_t)m * Fdim;
    dst[operm(k4 + 0)] = v.x; dst[operm(k4 + 1)] = v.y;
    dst[operm(k4 + 2)] = v.z; dst[operm(k4 + 3)] = v.w;
}

// Prep: g_Wt[r][o][k'] = rna(W[r][k][o])
__global__ void wt_prep(const float* __restrict__ W) {
    int f = blockIdx.x * 256 + threadIdx.x;       // 114688 threads
    int r = f >> 14, u = f & 16383, k4 = (u >> 8) << 2, o = u & 255;
    float* dst = g_Wt + ((size_t)r * OUTd + o) * Fdim;
#pragma unroll
    for (int j = 0; j < 4; j++) {
        float v = to_tf32(W[((size_t)r * (Fdim + RELd) + k4 + j) * OUTd + o]);
        dst[operm(k4 + j)] = v;
    }
}

// ---------------------------------------------------------------------------
// HW GEMM: tf32( X[m,:]@W[r] + c[r] ) -> g_Ht (r=0,1,3,4) or g_H3 (r=2,5,6)
// CTA tile: 128 m x 128 o. cp.async 2-stage, LDS.64 fragments on both operands.
__global__ __launch_bounds__(256, 2) void hw_mma(const float* __restrict__ W,
                                                 const float* __restrict__ We) {
    extern __shared__ float sm[];
    __shared__ float sCv[128];
    float* sA[2] = { sm, sm + XWBUF };
    float* sB[2] = { sm + 2 * XWBUF, sm + 3 * XWBUF };
    const uint32_t saU[2] = { smem_u32(sA[0]), smem_u32(sA[1]) };
    const uint32_t sbU[2] = { smem_u32(sB[0]), smem_u32(sB[1]) };

    const int tid = threadIdx.x, lane = tid & 31, wid = tid >> 5;
    const int warp_m = (wid & 3) * 32, warp_n = (wid >> 2) * 64;
    const int grp = lane >> 2, tg = lane & 3;

    const int r  = blockIdx.x >> 1;
    const int o0 = (blockIdx.x & 1) * 128;
    const int m0 = blockIdx.y * 128;

    if (tid < 128) {
        float s = 0.f;
#pragma unroll
        for (int d = 0; d < RELd; d++)
            s += We[r * RELd + d] * W[((size_t)r * (Fdim + RELd) + Fdim + d) * OUTd + o0 + tid];
        sCv[tid] = s;
    }

    const float* Xb = g_Xr + (size_t)m0 * Fdim;
    const float* Wt = g_Wt + ((size_t)r * OUTd + o0) * Fdim;

    float acc[2][8][4];
#pragma unroll
    for (int mt = 0; mt < 2; mt++)
#pragma unroll
        for (int nt = 0; nt < 8; nt++)
#pragma unroll
            for (int j = 0; j < 4; j++) acc[mt][nt][j] = 0.f;

    // per-chunk loader: rows of 32 permuted k's, linear copy
    auto loadc = [&](int k0, int s) {
#pragma unroll
        for (int i = 0; i < 4; i++) {
            int f = tid + i * 256, row = f >> 3, s4 = (f & 7) << 2;
            CPA16(saU[s] + (row * SB_STR + s4) * 4, Xb + (size_t)row * Fdim + k0 + s4);
            CPA16(sbU[s] + (row * SB_STR + s4) * 4, Wt + (size_t)row * Fdim + k0 + s4);
        }
    };

    const int NC = Fdim / KC;  // 8
    loadc(0, 0);  CPA_COMMIT();
    loadc(KC, 1); CPA_COMMIT();

    for (int c = 0; c < NC; c++) {
        const int buf = c & 1;
        if (c + 1 < NC) CPA_WAIT1(); else CPA_WAIT0();
        __syncthreads();

        const float* cA = sA[buf] + 2 * tg;
        const float* cB = sB[buf] + (warp_n + grp) * SB_STR + 2 * tg;
#pragma unroll
        for (int ks = 0; ks < 4; ks++) {
            const int kp = ks * 8;
            float2 va0 = *(const float2*)(cA + (warp_m + grp) * SB_STR + kp);
            float2 vb0 = *(const float2*)(cA + (warp_m + 8 + grp) * SB_STR + kp);
            float2 va1 = *(const float2*)(cA + (warp_m + 16 + grp) * SB_STR + kp);
            float2 vb1 = *(const float2*)(cA + (warp_m + 24 + grp) * SB_STR + kp);
            uint32_t a0[4] = { fbits(&va0.x), fbits(&vb0.x), fbits(&va0.y), fbits(&vb0.y) };
            uint32_t a1[4] = { fbits(&va1.x), fbits(&vb1.x), fbits(&va1.y), fbits(&vb1.y) };
#pragma unroll
            for (int nt = 0; nt < 8; nt++) {
                const float2 bv = *(const float2*)(cB + nt * 8 * SB_STR + kp);
                mma8(acc[0][nt], a0, fbits(&bv.x), fbits(&bv.y));
                mma8(acc[1][nt], a1, fbits(&bv.x), fbits(&bv.y));
            }
        }
        if (c + 2 < NC) {
            __syncthreads();
            loadc((c + 2) * KC, buf);
            CPA_COMMIT();
        }
    }

    const bool isId = (r == 2 || r == 5 || r == 6);
    if (isId) {
        const int zi = (r == 2) ? 0 : (r == 5) ? 1 : 2;
#pragma unroll
        for (int mt = 0; mt < 2; mt++) {
#pragma unroll
            for (int nt = 0; nt < 8; nt++) {
                const int ol = warp_n + nt * 8 + 2 * tg;
                const float2 cv = *(const float2*)(sCv + ol);
                const int o = o0 + ol;
                int mg = m0 + warp_m + mt * 16 + grp;
                int b = mg >> 10, n = mg & 1023;
                float* dst = g_H3 + (((size_t)(zi * Bx + b) * Nn + n) * OUTd) + o;
                *(float2*)dst = make_float2(to_tf32(acc[mt][nt][0] + cv.x),
                                            to_tf32(acc[mt][nt][1] + cv.y));
                mg += 8; b = mg >> 10; n = mg & 1023;
                dst = g_H3 + (((size_t)(zi * Bx + b) * Nn + n) * OUTd) + o;
                *(float2*)dst = make_float2(to_tf32(acc[mt][nt][2] + cv.x),
                                            to_tf32(acc[mt][nt][3] + cv.y));
            }
        }
    } else {
        const int ti = (r < 2) ? r : r - 1;   // 0,1,3,4 -> 0,1,2,3
#pragma unroll
        for (int mt = 0; mt < 2; mt++) {
#pragma unroll
            for (int nt = 0; nt < 8; nt++) {
                const int ol = warp_n + nt * 8 + 2 * tg;
                const float2 cv = *(const float2*)(sCv + ol);
                const int o = o0 + ol;
                int mg = m0 + warp_m + mt * 16 + grp;
                {
                    int b = mg >> 10, n = mg & 1023, np = operm(n);
                    float* base = g_Ht + ((size_t)(ti * Bx + b) * OUTd + o) * Nn;
                    base[np]      = to_tf32(acc[mt][nt][0] + cv.x);
                    base[Nn + np] = to_tf32(acc[mt][nt][1] + cv.y);
                }
                mg += 8;
                {
                    int b = mg >> 10, n = mg & 1023, np = operm(n);
                    float* base = g_Ht + ((size_t)(ti * Bx + b) * OUTd + o) * Nn;
                    base[np]      = to_tf32(acc[mt][nt][2] + cv.x);
                    base[Nn + np] = to_tf32(acc[mt][nt][3] + cv.y);
                }
            }
        }
    }
}

// ---------------------------------------------------------------------------
// One relation pass: P[p][b] = A(_or_At) @ H.  2-stage cp.async, float2 B frags.
template <bool TR>
__device__ __forceinline__ void agg_load(uint32_t sa, uint32_t sb,
                                         const float* Ab, const float* Hb,
                                         int n0, int k0, int tid) {
#pragma unroll
    for (int i = 0; i < 4; i++) {
        int f = tid + i * 256;
        if (!TR) {
            int m = f >> 3, k4 = (f & 7) << 2;
            CPA16(sa + (m * SA_STR + k4) * 4, Ab + (size_t)(n0 + m) * Nn + k0 + k4);
        } else {
            int kk = f >> 5, n4 = (f & 31) << 2;
            CPA16(sa + (kk * ST_STR + n4) * 4, Ab + (size_t)(k0 + kk) * Nn + n0 + n4);
        }
        int o = f >> 3, s4 = (f & 7) << 2;
        CPA16(sb + (o * SB_STR + s4) * 4, Hb + (size_t)o * Nn + k0 + s4);
    }
}

template <bool TR>
__device__ __forceinline__ void agg_body(const float* Ab, const float* Hb,
                                         float* Pout, int n0, int o0) {
    extern __shared__ float sm[];
    float* sA[2] = { sm, sm + ABUF };
    float* sB[2] = { sm + 2 * ABUF, sm + 2 * ABUF + BBUF_AG };
    const uint32_t saU[2] = { smem_u32(sA[0]), smem_u32(sA[1]) };
    const uint32_t sbU[2] = { smem_u32(sB[0]), smem_u32(sB[1]) };

    const int tid = threadIdx.x, lane = tid & 31, wid = tid >> 5;
    const int warp_m = (wid & 3) * 32, warp_n = (wid >> 2) * 64;
    const int grp = lane >> 2, tg = lane & 3;

    float acc[2][8][4];
#pragma unroll
    for (int mt = 0; mt < 2; mt++)
#pragma unroll
        for (int nt = 0; nt < 8; nt++)
#pragma unroll
            for (int j = 0; j < 4; j++) acc[mt][nt][j] = 0.f;

    const int NC = Nn / KC;  // 32
    agg_load<TR>(saU[0], sbU[0], Ab, Hb, n0, 0, tid);
    CPA_COMMIT();
    agg_load<TR>(saU[1], sbU[1], Ab, Hb, n0, KC, tid);
    CPA_COMMIT();

    for (int c = 0; c < NC; c++) {
        const int buf = c & 1;
        if (c + 1 < NC) CPA_WAIT1(); else CPA_WAIT0();
        __syncthreads();

        const float* cA = sA[buf];
        const float* cB = sB[buf] + (warp_n + grp) * SB_STR + 2 * tg;
#pragma unroll
        for (int ks = 0; ks < 4; ks++) {
            const int k = ks * 8;
            uint32_t afr[2][4];
#pragma unroll
            for (int mt = 0; mt < 2; mt++) {
                int rr = warp_m + mt * 16 + grp, cc = k + tg;
                if (!TR) {
                    afr[mt][0] = fbits(cA + rr * SA_STR + cc);
                    afr[mt][1] = fbits(cA + (rr + 8) * SA_STR + cc);
                    afr[mt][2] = fbits(cA + rr * SA_STR + cc + 4);
                    afr[mt][3] = fbits(cA + (rr + 8) * SA_STR + cc + 4);
                } else {
                    afr[mt][0] = fbits(cA + cc * ST_STR + rr);
                    afr[mt][1] = fbits(cA + cc * ST_STR + rr + 8);
                    afr[mt][2] = fbits(cA + (cc + 4) * ST_STR + rr);
                    afr[mt][3] = fbits(cA + (cc + 4) * ST_STR + rr + 8);
                }
            }
#pragma unroll
            for (int nt = 0; nt < 8; nt++) {
                const float2 bv = *(const float2*)(cB + nt * 8 * SB_STR + k);
                uint32_t b0 = fbits(&bv.x), b1 = fbits(&bv.y);
                mma8(acc[0][nt], afr[0], b0, b1);
                mma8(acc[1][nt], afr[1], b0, b1);
            }
        }
        if (c + 2 < NC) {
            __syncthreads();
            agg_load<TR>(saU[buf], sbU[buf], Ab, Hb, n0, (c + 2) * KC, tid);
            CPA_COMMIT();
        }
    }

#pragma unroll
    for (int mt = 0; mt < 2; mt++) {
#pragma unroll
        for (int nt = 0; nt < 8; nt++) {
            const int o = o0 + warp_n + nt * 8 + 2 * tg;
#pragma unroll
            for (int h = 0; h < 2; h++) {
                const int n = n0 + warp_m + mt * 16 + grp + h * 8;
                *(float2*)(Pout + (size_t)n * OUTd + o) =
                    make_float2(acc[mt][nt][2 * h], acc[mt][nt][2 * h + 1]);
            }
        }
    }
}

__global__ __launch_bounds__(256, 2) void agg_pass(const float* __restrict__ A1,
                                                   const float* __restrict__ A2) {
    const int o0 = blockIdx.x * 128;
    const int n0 = blockIdx.y * 128;
    const int z  = blockIdx.z;
    const int b  = z & 7;
    const int p  = z >> 3;                   // 0:A1@H0 1:A2@H1 2:A1t@H3 3:A2t@H4
    const int q  = p & 1;
    const float* Ab = (q == 0 ? A1 : A2) + (size_t)b * Nn * Nn;
    const float* Hb = g_Ht + ((size_t)(p * Bx + b) * OUTd + o0) * Nn;
    float* Pout = g_P + (size_t)p * PSTR + ((size_t)b * Nn) * OUTd;

    if (p < 2) agg_body<false>(Ab, Hb, Pout, n0, o0);
    else       agg_body<true >(Ab, Hb, Pout, n0, o0);
}

// ---------------------------------------------------------------------------
__global__ __launch_bounds__(256) void fold_kernel(const float* __restrict__ bias,
                                                   float* __restrict__ out) {
    const int idx = (blockIdx.x * 256 + threadIdx.x) * 4;
    float4 v = *(const float4*)(g_P + idx);
    float4 t;
#pragma unroll
    for (int p = 1; p < 4; p++) {
        t = *(const float4*)(g_P + (size_t)p * PSTR + idx);
        v.x = fmaxf(v.x, t.x); v.y = fmaxf(v.y, t.y);
        v.z = fmaxf(v.z, t.z); v.w = fmaxf(v.w, t.w);
    }
#pragma unroll
    for (int zi = 0; zi < 3; zi++) {
        t = *(const float4*)(g_H3 + (size_t)zi * PSTR + idx);
        v.x = fmaxf(v.x, t.x); v.y = fmaxf(v.y, t.y);
        v.z = fmaxf(v.z, t.z); v.w = fmaxf(v.w, t.w);
    }
    const int bi = idx & (Nn * OUTd - 1);
    t = *(const float4*)(bias + bi);
    v.x += t.x; v.y += t.y; v.z += t.z; v.w += t.w;
    *(float4*)(out + idx) = v;
}

// ---------------------------------------------------------------------------
extern "C" void kernel_launch(void* const* d_in, const int* in_sizes, int n_in,
                              void* d_out, int out_size) {
    const float* X    = (const float*)d_in[0];
    const float* A1   = (const float*)d_in[1];
    const float* A2   = (const float*)d_in[2];
    const float* W    = (const float*)d_in[3];
    const float* We   = (const float*)d_in[4];
    const float* bias = (const float*)d_in[5];
    float* out = (float*)d_out;

    const int hw_smem = HW_SMEM_FLOATS * sizeof(float);
    const int ag_smem = AG_SMEM_FLOATS * sizeof(float);
    cudaFuncSetAttribute(hw_mma,   cudaFuncAttributeMaxDynamicSharedMemorySize, hw_smem);
    cudaFuncSetAttribute(agg_pass, cudaFuncAttributeMaxDynamicSharedMemorySize, ag_smem);

    xp_kernel<<<2048, 256>>>(X);
    wt_prep<<<448, 256>>>(W);

    dim3 gHW(14, 64);                        // (r*2+oh), m-tiles
    hw_mma<<<gHW, 256, hw_smem>>>(W, We);

    dim3 gAgg(2, 8, 32);
    agg_pass<<<gAgg, 256, ag_smem>>>(A1, A2);

    fold_kernel<<<(Bx * Nn * OUTd) / 1024, 256>>>(bias, out);
}